// round 4
// baseline (speedup 1.0000x reference)
#include <cuda_runtime.h>
#include <cuda_bf16.h>

// out[i][k] = s_{k-1}(x_i) - s_k(x_i),  s_j(x) = relu(1 - relu(xb_j - x)/(h_j + 1e-9))
// with virtual s_{-1} = 1, s_{n_el} = 0.  Only the +-2 neighborhood of the
// containing interval can be nonzero (computed with the exact reference
// arithmetic), so each warp streams one zero row and merges the <=4 patched
// columns into the fill — no __syncthreads, no per-block serial tail.

#define THREADS_PER_BLOCK 256
#define WARPS_PER_BLOCK (THREADS_PER_BLOCK / 32)

__global__ void __launch_bounds__(THREADS_PER_BLOCK)
hat_basis_warp_kernel(const float* __restrict__ x_eval,
                      const float* __restrict__ x_full,
                      float* __restrict__ out,
                      int n_points, int n_nodes)
{
    const int n_el = n_nodes - 1;
    const int row  = blockIdx.x * WARPS_PER_BLOCK + (threadIdx.x >> 5);
    const int lane = threadIdx.x & 31;
    if (row >= n_points) return;

    const float x = __ldg(&x_eval[row]);

    // Binary search: largest j in [0, n_el-1] with x_full[j] <= x.
    // All lanes redundant; same-address loads broadcast in L1.
    int lo = 0, hi = n_el;
    while (hi - lo > 1) {
        const int mid = (lo + hi) >> 1;
        if (__ldg(&x_full[mid]) <= x) lo = mid; else hi = mid;
    }
    const int j = lo;

    // s_k with the exact reference arithmetic, k in [j-2, j+2] (clamped).
    float S[5];
#pragma unroll
    for (int t = 0; t < 5; ++t) {
        const int k = j - 2 + t;
        float s;
        if (k < 0) {
            s = 1.0f;
        } else if (k >= n_el) {
            s = 0.0f;
        } else {
            const float xa = __ldg(&x_full[k]);
            const float xb = __ldg(&x_full[k + 1]);
            const float h  = xb - xa;
            const float l1 = fmaxf(xb - x, 0.0f);
            s = fmaxf(1.0f - l1 / (h + 1e-9f), 0.0f);
        }
        S[t] = s;
    }
    const float d0 = S[0] - S[1];   // column j-1
    const float d1 = S[1] - S[2];   // column j
    const float d2 = S[2] - S[3];   // column j+1
    const float d3 = S[3] - S[4];   // column j+2
    const int   c0 = j - 1;         // first (possibly virtual) patched column

    const long long base = (long long)row * (long long)n_nodes;
    float* __restrict__ p = out + base;

    // Row start is not 16B-aligned in general (n_nodes = 2049): head/tail scalars.
    const int bm   = (int)(base & 3);
    int head = (4 - bm) & 3;
    if (head > n_nodes) head = n_nodes;
    const int nb   = (n_nodes - head) >> 2;          // aligned float4 count
    const int tail = n_nodes - head - (nb << 2);

    // patch-value selector: column col -> d[col - c0] if in [0,3] else 0
    auto pv = [&](int col) -> float {
        const int k = col - c0;
        return (k == 0) ? d0 : (k == 1) ? d1 : (k == 2) ? d2 : (k == 3) ? d3 : 0.0f;
    };

    if (lane < head)
        __stcs(&p[lane], pv(lane));

    if (lane < tail) {
        const int col = head + (nb << 2) + lane;
        __stcs(&p[col], pv(col));
    }

    // Body: contiguous, 16B-aligned float4 stream with merged patch.
    float4* __restrict__ b4 = reinterpret_cast<float4*>(p + head);
    const float4 z = make_float4(0.f, 0.f, 0.f, 0.f);
#pragma unroll 4
    for (int v = lane; v < nb; v += 32) {
        const int cb = head + (v << 2);              // first column of this vector
        float4 val = z;
        if (cb + 3 >= c0 && cb <= c0 + 3) {          // overlaps patch window (rare)
            val.x = pv(cb + 0);
            val.y = pv(cb + 1);
            val.z = pv(cb + 2);
            val.w = pv(cb + 3);
        }
        __stcs(&b4[v], val);
    }
}

extern "C" void kernel_launch(void* const* d_in, const int* in_sizes, int n_in,
                              void* d_out, int out_size) {
    const float* x_eval = (const float*)d_in[0];   // (n_points, 1) float32
    const float* x_full = (const float*)d_in[1];   // (n_nodes,)  float32, sorted
    float* out = (float*)d_out;

    const int n_points = in_sizes[0];
    const int n_nodes  = in_sizes[1];

    const int blocks = (n_points + WARPS_PER_BLOCK - 1) / WARPS_PER_BLOCK;
    hat_basis_warp_kernel<<<blocks, THREADS_PER_BLOCK>>>(x_eval, x_full, out,
                                                         n_points, n_nodes);
}